// round 3
// baseline (speedup 1.0000x reference)
#include <cuda_runtime.h>
#include <cuda_bf16.h>
#include <cstdint>

#define HIDDEN 1024
#define NH 8
#define NKV 2
#define HD 128
#define SEQ 4096
#define WIN 2048

// ---------------- scratch (device globals: allocation-free) ----------------
__device__ float g_q[NH * SEQ * HD];     // [h][s][d]
__device__ float g_k[NKV * SEQ * HD];    // [kv][s][d]
__device__ float g_v[NKV * SEQ * HD];    // [kv][s][d]
__device__ float g_ctx[SEQ * HIDDEN];    // [s][h*128+d]

// ---------------- helpers ----------------
__device__ __forceinline__ float cvt_tf32(float x) {
    uint32_t u;
    asm("cvt.rna.tf32.f32 %0, %1;" : "=r"(u) : "f"(x));
    return __uint_as_float(u);
}

__device__ __forceinline__ void mma_tf32(float* c, const uint32_t* a, const uint32_t* b) {
    asm volatile(
        "mma.sync.aligned.m16n8k8.row.col.f32.tf32.tf32.f32 "
        "{%0,%1,%2,%3}, {%4,%5,%6,%7}, {%8,%9}, {%0,%1,%2,%3};\n"
        : "+f"(c[0]), "+f"(c[1]), "+f"(c[2]), "+f"(c[3])
        : "r"(a[0]), "r"(a[1]), "r"(a[2]), "r"(a[3]), "r"(b[0]), "r"(b[1]));
}

// ---------------- GEMM: C[M,N] = A[M,K] @ W[N,K]^T  (tf32 MMA) ----------------
// MODE 0: A = hidden_states (arg), W = {wq|wk|wv} by block, out -> g_q/g_k/g_v [h][s][d]
// MODE 1: A = g_ctx (read as device symbol IN KERNEL — passing it as a host-side
//         kernel arg is invalid, that was the round-1 bug), W = wo, out -> d_out
#define GBM 128
#define GBN 128
#define GBK 16
#define GLD 20   // pad 16->20: conflict-free frag loads, 16B-aligned rows

template <int MODE>
__global__ __launch_bounds__(256) void gemm_kernel(
    const float* __restrict__ Aarg,
    const float* __restrict__ W0,   // wq (MODE0) / wo (MODE1)
    const float* __restrict__ W1,   // wk
    const float* __restrict__ W2,   // wv
    float* __restrict__ Out)        // d_out (MODE1)
{
    __shared__ float As[GBM][GLD];
    __shared__ float Bs[GBN][GLD];

    const float* A = (MODE == 0) ? Aarg : (const float*)g_ctx;

    const int tid  = threadIdx.x;
    const int lane = tid & 31;
    const int warp = tid >> 5;
    const int wm   = warp & 3;       // 0..3
    const int wn   = warp >> 2;      // 0..1
    const int gr   = lane >> 2;      // 0..7
    const int gc   = lane & 3;       // 0..3

    const int bn = blockIdx.x;
    const int m0 = blockIdx.y * GBM;

    // B (weight) pointer for this n-block (BN=128 aligned to weight boundaries)
    const float* Bp;
    if (MODE == 0) {
        if (bn < 8)       Bp = W0 + (size_t)bn * 128 * HIDDEN;
        else if (bn < 10) Bp = W1 + (size_t)(bn - 8) * 128 * HIDDEN;
        else              Bp = W2 + (size_t)(bn - 10) * 128 * HIDDEN;
    } else {
        Bp = W0 + (size_t)bn * 128 * HIDDEN;
    }

    float acc[2][8][4];
#pragma unroll
    for (int i = 0; i < 2; i++)
#pragma unroll
        for (int j = 0; j < 8; j++)
#pragma unroll
            for (int r = 0; r < 4; r++) acc[i][j][r] = 0.f;

    const int lr = tid >> 2;          // 0..63
    const int lc = (tid & 3) << 2;    // 0,4,8,12

    for (int kb = 0; kb < HIDDEN; kb += GBK) {
#pragma unroll
        for (int rr = 0; rr < 2; rr++) {
            const int row = lr + rr * 64;
            float4 a4 = *(const float4*)(A + (size_t)(m0 + row) * HIDDEN + kb + lc);
            As[row][lc + 0] = cvt_tf32(a4.x);
            As[row][lc + 1] = cvt_tf32(a4.y);
            As[row][lc + 2] = cvt_tf32(a4.z);
            As[row][lc + 3] = cvt_tf32(a4.w);
            float4 b4 = *(const float4*)(Bp + (size_t)row * HIDDEN + kb + lc);
            Bs[row][lc + 0] = cvt_tf32(b4.x);
            Bs[row][lc + 1] = cvt_tf32(b4.y);
            Bs[row][lc + 2] = cvt_tf32(b4.z);
            Bs[row][lc + 3] = cvt_tf32(b4.w);
        }
        __syncthreads();

#pragma unroll
        for (int kk = 0; kk < GBK; kk += 8) {
            uint32_t afr[2][4];
#pragma unroll
            for (int i = 0; i < 2; i++) {
                const int mr = wm * 32 + i * 16;
                afr[i][0] = __float_as_uint(As[mr + gr][kk + gc]);
                afr[i][1] = __float_as_uint(As[mr + gr + 8][kk + gc]);
                afr[i][2] = __float_as_uint(As[mr + gr][kk + gc + 4]);
                afr[i][3] = __float_as_uint(As[mr + gr + 8][kk + gc + 4]);
            }
#pragma unroll
            for (int j = 0; j < 8; j++) {
                const int nr = wn * 64 + j * 8;
                uint32_t bfr[2];
                bfr[0] = __float_as_uint(Bs[nr + gr][kk + gc]);
                bfr[1] = __float_as_uint(Bs[nr + gr][kk + gc + 4]);
#pragma unroll
                for (int i = 0; i < 2; i++) mma_tf32(acc[i][j], afr[i], bfr);
            }
        }
        __syncthreads();
    }

    // epilogue
#pragma unroll
    for (int i = 0; i < 2; i++) {
        const int row0 = m0 + wm * 32 + i * 16 + gr;
#pragma unroll
        for (int j = 0; j < 8; j++) {
            const int nl = wn * 64 + j * 8 + gc * 2;   // 0..127 within block
            if (MODE == 0) {
                float* ob;
                if (bn < 8)       ob = g_q + (size_t)bn * SEQ * HD;
                else if (bn < 10) ob = g_k + (size_t)(bn - 8) * SEQ * HD;
                else              ob = g_v + (size_t)(bn - 10) * SEQ * HD;
                ob[(size_t)row0 * HD + nl]           = acc[i][j][0];
                ob[(size_t)row0 * HD + nl + 1]       = acc[i][j][1];
                ob[(size_t)(row0 + 8) * HD + nl]     = acc[i][j][2];
                ob[(size_t)(row0 + 8) * HD + nl + 1] = acc[i][j][3];
            } else {
                const int nc = bn * 128 + nl;
                Out[(size_t)row0 * HIDDEN + nc]           = acc[i][j][0];
                Out[(size_t)row0 * HIDDEN + nc + 1]       = acc[i][j][1];
                Out[(size_t)(row0 + 8) * HIDDEN + nc]     = acc[i][j][2];
                Out[(size_t)(row0 + 8) * HIDDEN + nc + 1] = acc[i][j][3];
            }
        }
    }
}

// ---------------- RoPE (in place on g_q, g_k) ----------------
__global__ void rope_kernel() {
    const int row = blockIdx.x;          // 0 .. (NH+NKV)*SEQ-1
    const int d   = threadIdx.x;         // 0..63
    float* base;
    int s;
    if (row < NH * SEQ) { base = g_q + (size_t)row * HD; s = row & (SEQ - 1); }
    else                { base = g_k + (size_t)(row - NH * SEQ) * HD; s = row & (SEQ - 1); }
    const float inv = powf(10000.f, -(float)d / 64.f);
    float sn, cs;
    sincosf((float)s * inv, &sn, &cs);
    const float x1 = base[d];
    const float x2 = base[d + 64];
    base[d]      = x1 * cs - x2 * sn;
    base[d + 64] = x2 * cs + x1 * sn;
}

// ---------------- Flash attention (sliding window, GQA, tf32 MMA) ----------------
#define AQ 64
#define AKV 64
#define QLD 132   // 128+4: conflict-free frag loads
#define VLD 68    // 64+4
#define PLD 68

#define SQ_OFF 0
#define SK_OFF (AQ * QLD)                 // 8448
#define SV_OFF (SK_OFF + AQ * QLD)        // 16896
#define SP_OFF (SV_OFF + HD * VLD)        // 25600
#define ATTN_SMEM ((SP_OFF + AQ * PLD) * 4)   // 119808 bytes

__global__ __launch_bounds__(128) void attn_kernel() {
    extern __shared__ float sm[];
    float* sQ  = sm + SQ_OFF;
    float* sK  = sm + SK_OFF;
    float* sVt = sm + SV_OFF;
    float* sP  = sm + SP_OFF;

    const int tid  = threadIdx.x;
    const int lane = tid & 31;
    const int warp = tid >> 5;           // 0..3, rows [warp*16, warp*16+16)
    const int gr   = lane >> 2;
    const int gc   = lane & 3;

    const int h  = blockIdx.y;
    const int q0 = blockIdx.x * AQ;
    const int kv = h >> 2;               // repeat_interleave: qh -> qh/4

    const float* Qg = g_q + ((size_t)h * SEQ + q0) * HD;
    const float* Kg = g_k + (size_t)kv * SEQ * HD;
    const float* Vg = g_v + (size_t)kv * SEQ * HD;

    const float qscale = 0.08838834764831845f;   // 1/sqrt(128)

    // stage Q (scaled, tf32)
    for (int idx = tid; idx < AQ * (HD / 4); idx += 128) {
        const int r  = idx >> 5;
        const int c4 = (idx & 31) << 2;
        float4 v = *(const float4*)(Qg + (size_t)r * HD + c4);
        sQ[r * QLD + c4 + 0] = cvt_tf32(v.x * qscale);
        sQ[r * QLD + c4 + 1] = cvt_tf32(v.y * qscale);
        sQ[r * QLD + c4 + 2] = cvt_tf32(v.z * qscale);
        sQ[r * QLD + c4 + 3] = cvt_tf32(v.w * qscale);
    }

    float o[16][4];
#pragma unroll
    for (int n = 0; n < 16; n++)
#pragma unroll
        for (int r = 0; r < 4; r++) o[n][r] = 0.f;
    float mst0 = -1e30f, mst1 = -1e30f;
    float lst0 = 0.f,    lst1 = 0.f;

    const int jlow = q0 - WIN + 1;
    const int t0 = (jlow > 0 ? jlow : 0) >> 6;
    const int t1 = (q0 + AQ - 1) >> 6;

    const int irow0 = q0 + warp * 16 + gr;

    for (int t = t0; t <= t1; t++) {
        const int j0 = t * 64;
        __syncthreads();   // protect K/Vt overwrite (and first-iter Q visibility)

        for (int idx = tid; idx < AKV * (HD / 4); idx += 128) {
            const int r  = idx >> 5;
            const int c4 = (idx & 31) << 2;
            float4 v = *(const float4*)(Kg + (size_t)(j0 + r) * HD + c4);
            sK[r * QLD + c4 + 0] = cvt_tf32(v.x);
            sK[r * QLD + c4 + 1] = cvt_tf32(v.y);
            sK[r * QLD + c4 + 2] = cvt_tf32(v.z);
            sK[r * QLD + c4 + 3] = cvt_tf32(v.w);
        }
        for (int idx = tid; idx < AKV * (HD / 4); idx += 128) {
            const int j  = idx >> 5;
            const int c4 = (idx & 31) << 2;
            float4 v = *(const float4*)(Vg + (size_t)(j0 + j) * HD + c4);
            sVt[(c4 + 0) * VLD + j] = cvt_tf32(v.x);
            sVt[(c4 + 1) * VLD + j] = cvt_tf32(v.y);
            sVt[(c4 + 2) * VLD + j] = cvt_tf32(v.z);
            sVt[(c4 + 3) * VLD + j] = cvt_tf32(v.w);
        }
        __syncthreads();

        // S = Q K^T
        float sc[8][4];
#pragma unroll
        for (int j = 0; j < 8; j++)
#pragma unroll
            for (int r = 0; r < 4; r++) sc[j][r] = 0.f;

#pragma unroll
        for (int kk = 0; kk < 16; kk++) {
            uint32_t afr[4];
            const int mr = warp * 16;
            afr[0] = __float_as_uint(sQ[(mr + gr) * QLD + kk * 8 + gc]);
            afr[1] = __float_as_uint(sQ[(mr + gr + 8) * QLD + kk * 8 + gc]);
            afr[2] = __float_as_uint(sQ[(mr + gr) * QLD + kk * 8 + gc + 4]);
            afr[3] = __float_as_uint(sQ[(mr + gr + 8) * QLD + kk * 8 + gc + 4]);
#pragma unroll
            for (int j = 0; j < 8; j++) {
                uint32_t bfr[2];
                bfr[0] = __float_as_uint(sK[(j * 8 + gr) * QLD + kk * 8 + gc]);
                bfr[1] = __float_as_uint(sK[(j * 8 + gr) * QLD + kk * 8 + gc + 4]);
                mma_tf32(sc[j], afr, bfr);
            }
        }

        // mask: valid = (j <= i) && (j > i - WIN)
#pragma unroll
        for (int j = 0; j < 8; j++) {
            const int jg = j0 + j * 8 + gc * 2;
#pragma unroll
            for (int r = 0; r < 4; r++) {
                const int jc = jg + (r & 1);
                const int ic = irow0 + ((r >> 1) << 3);
                if (jc > ic || jc <= ic - WIN) sc[j][r] = -1e30f;
            }
        }

        // online softmax
        float rm0 = -1e30f, rm1 = -1e30f;
#pragma unroll
        for (int j = 0; j < 8; j++) {
            rm0 = fmaxf(rm0, fmaxf(sc[j][0], sc[j][1]));
            rm1 = fmaxf(rm1, fmaxf(sc[j][2], sc[j][3]));
        }
        rm0 = fmaxf(rm0, __shfl_xor_sync(0xffffffffu, rm0, 1));
        rm0 = fmaxf(rm0, __shfl_xor_sync(0xffffffffu, rm0, 2));
        rm1 = fmaxf(rm1, __shfl_xor_sync(0xffffffffu, rm1, 1));
        rm1 = fmaxf(rm1, __shfl_xor_sync(0xffffffffu, rm1, 2));

        const float mn0 = fmaxf(mst0, rm0);
        const float mn1 = fmaxf(mst1, rm1);
        const float al0 = __expf(mst0 - mn0);
        const float al1 = __expf(mst1 - mn1);
        mst0 = mn0; mst1 = mn1;
        lst0 *= al0; lst1 *= al1;
#pragma unroll
        for (int n = 0; n < 16; n++) {
            o[n][0] *= al0; o[n][1] *= al0;
            o[n][2] *= al1; o[n][3] *= al1;
        }

        float rs0 = 0.f, rs1 = 0.f;
        const int pr0 = (warp * 16 + gr) * PLD;
        const int pr1 = (warp * 16 + gr + 8) * PLD;
#pragma unroll
        for (int j = 0; j < 8; j++) {
            const float p0 = __expf(sc[j][0] - mn0);
            const float p1 = __expf(sc[j][1] - mn0);
            const float p2 = __expf(sc[j][2] - mn1);
            const float p3 = __expf(sc[j][3] - mn1);
            rs0 += p0 + p1;
            rs1 += p2 + p3;
            const int cbase = j * 8 + gc * 2;
            sP[pr0 + cbase]     = cvt_tf32(p0);
            sP[pr0 + cbase + 1] = cvt_tf32(p1);
            sP[pr1 + cbase]     = cvt_tf32(p2);
            sP[pr1 + cbase + 1] = cvt_tf32(p3);
        }
        rs0 += __shfl_xor_sync(0xffffffffu, rs0, 1);
        rs0 += __shfl_xor_sync(0xffffffffu, rs0, 2);
        rs1 += __shfl_xor_sync(0xffffffffu, rs1, 1);
        rs1 += __shfl_xor_sync(0xffffffffu, rs1, 2);
        lst0 += rs0; lst1 += rs1;

        __syncwarp();

        // O += P V
#pragma unroll
        for (int kk = 0; kk < 8; kk++) {
            uint32_t afr[4];
            const int mr = warp * 16;
            afr[0] = __float_as_uint(sP[(mr + gr) * PLD + kk * 8 + gc]);
            afr[1] = __float_as_uint(sP[(mr + gr + 8) * PLD + kk * 8 + gc]);
            afr[2] = __float_as_uint(sP[(mr + gr) * PLD + kk * 8 + gc + 4]);
            afr[3] = __float_as_uint(sP[(mr + gr + 8) * PLD + kk * 8 + gc + 4]);
#pragma unroll
            for (int n = 0; n < 16; n++) {
                uint32_t bfr[2];
                bfr[0] = __float_as_uint(sVt[(n * 8 + gr) * VLD + kk * 8 + gc]);
                bfr[1] = __float_as_uint(sVt[(n * 8 + gr) * VLD + kk * 8 + gc + 4]);
                mma_tf32(o[n], afr, bfr);
            }
        }
    }

    const float inv0 = 1.f / lst0;
    const float inv1 = 1.f / lst1;
#pragma unroll
    for (int n = 0; n < 16; n++) {
        const int col = h * HD + n * 8 + gc * 2;
        g_ctx[(size_t)irow0 * HIDDEN + col]           = o[n][0] * inv0;
        g_ctx[(size_t)irow0 * HIDDEN + col + 1]       = o[n][1] * inv0;
        g_ctx[(size_t)(irow0 + 8) * HIDDEN + col]     = o[n][2] * inv1;
        g_ctx[(size_t)(irow0 + 8) * HIDDEN + col + 1] = o[n][3] * inv1;
    }
}

// ---------------- launch ----------------
extern "C" void kernel_launch(void* const* d_in, const int* in_sizes, int n_in,
                              void* d_out, int out_size) {
    const float* hs = (const float*)d_in[0];
    const float* wq = (const float*)d_in[1];
    const float* wk = (const float*)d_in[2];
    const float* wv = (const float*)d_in[3];
    const float* wo = (const float*)d_in[4];
    float* out = (float*)d_out;

    cudaFuncSetAttribute(attn_kernel, cudaFuncAttributeMaxDynamicSharedMemorySize, ATTN_SMEM);

    gemm_kernel<0><<<dim3(12, 32), 256>>>(hs, wq, wk, wv, nullptr);
    rope_kernel<<<(NH + NKV) * SEQ, 64>>>();
    attn_kernel<<<dim3(SEQ / AQ, NH), 128, ATTN_SMEM>>>();
    gemm_kernel<1><<<dim3(8, 32), 256>>>(nullptr, wo, nullptr, nullptr, out);
}

// round 5
// speedup vs baseline: 1.3696x; 1.3696x over previous
#include <cuda_runtime.h>
#include <cstdint>

#define HIDDEN 1024
#define NH 8
#define NKV 2
#define HD 128
#define SEQ 4096
#define WIN 2048

// ---------------- device-global scratch ----------------
__device__ float g_q[NH * SEQ * HD];      // [h][s][d]  (tf32 after rope)
__device__ float g_k[NKV * SEQ * HD];     // [kv][s][d] (tf32 after rope)
__device__ float g_v[NKV * SEQ * HD];     // [kv][s][d] (tf32 from gemm0 epilogue)
__device__ float g_ctx[SEQ * HIDDEN];     // [s][h*128+d] (tf32 from attn epilogue)
__device__ float g_hs[SEQ * HIDDEN];      // tf32 copy of hidden_states
__device__ float g_wq[NH * HD * HIDDEN];  // tf32 weights
__device__ float g_wk[NKV * HD * HIDDEN];
__device__ float g_wv[NKV * HD * HIDDEN];
__device__ float g_wo[HIDDEN * NH * HD];
__device__ float g_rcos[SEQ * 64];
__device__ float g_rsin[SEQ * 64];

// ---------------- helpers ----------------
__device__ __forceinline__ float cvt_tf32(float x) {
    uint32_t u;
    asm("cvt.rna.tf32.f32 %0, %1;" : "=r"(u) : "f"(x));
    return __uint_as_float(u);
}

__device__ __forceinline__ void mma_tf32(float* c, const uint32_t* a, const uint32_t* b) {
    asm volatile(
        "mma.sync.aligned.m16n8k8.row.col.f32.tf32.tf32.f32 "
        "{%0,%1,%2,%3}, {%4,%5,%6,%7}, {%8,%9}, {%0,%1,%2,%3};\n"
        : "+f"(c[0]), "+f"(c[1]), "+f"(c[2]), "+f"(c[3])
        : "r"(a[0]), "r"(a[1]), "r"(a[2]), "r"(a[3]), "r"(b[0]), "r"(b[1]));
}

__device__ __forceinline__ void cp16(uint32_t dst, const void* src) {
    asm volatile("cp.async.cg.shared.global [%0], [%1], 16;" :: "r"(dst), "l"(src));
}
__device__ __forceinline__ void cp_commit() { asm volatile("cp.async.commit_group;"); }
template <int N>
__device__ __forceinline__ void cp_wait() { asm volatile("cp.async.wait_group %0;" :: "n"(N)); }

// ---------------- prep: tf32-convert hs + weights ----------------
__global__ void prep_kernel(const float* __restrict__ hs, const float* __restrict__ wq,
                            const float* __restrict__ wk, const float* __restrict__ wv,
                            const float* __restrict__ wo) {
    const int64_t N0 = (int64_t)SEQ * HIDDEN;            // 4M
    const int64_t N1 = (int64_t)NH * HD * HIDDEN;        // 1M
    const int64_t N2 = (int64_t)NKV * HD * HIDDEN;       // 256K
    const int64_t NT = (N0 + N1 + 2 * N2 + N1) >> 2;     // float4 count
    for (int64_t i = blockIdx.x * (int64_t)blockDim.x + threadIdx.x; i < NT;
         i += (int64_t)gridDim.x * blockDim.x) {
        int64_t e = i << 2;
        const float* src; float* dst; int64_t off;
        if (e < N0)                     { src = hs; dst = g_hs; off = e; }
        else if (e < N0 + N1)           { src = wq; dst = g_wq; off = e - N0; }
        else if (e < N0 + N1 + N2)      { src = wk; dst = g_wk; off = e - N0 - N1; }
        else if (e < N0 + N1 + 2 * N2)  { src = wv; dst = g_wv; off = e - N0 - N1 - N2; }
        else                            { src = wo; dst = g_wo; off = e - N0 - N1 - 2 * N2; }
        float4 v = *(const float4*)(src + off);
        v.x = cvt_tf32(v.x); v.y = cvt_tf32(v.y); v.z = cvt_tf32(v.z); v.w = cvt_tf32(v.w);
        *(float4*)(dst + off) = v;
    }
}

// ---------------- rope table (exact same math as the passing kernel) ----------------
__global__ void rope_table_kernel() {
    const int s = blockIdx.x;
    const int d = threadIdx.x;
    const float inv = powf(10000.f, -(float)d / 64.f);
    float sn, cs;
    sincosf((float)s * inv, &sn, &cs);
    g_rcos[s * 64 + d] = cs;
    g_rsin[s * 64 + d] = sn;
}

// ---------------- rope (in place, writes tf32) ----------------
__global__ __launch_bounds__(256) void rope_kernel() {
    const int row = blockIdx.x * 4 + (threadIdx.x >> 6);   // 0 .. 10*SEQ-1
    const int d   = threadIdx.x & 63;
    float* base;
    if (row < NH * SEQ) base = g_q + (size_t)row * HD;
    else                base = g_k + (size_t)(row - NH * SEQ) * HD;
    const int s = row & (SEQ - 1);
    const float cs = g_rcos[s * 64 + d];
    const float sn = g_rsin[s * 64 + d];
    const float x1 = base[d];
    const float x2 = base[d + 64];
    base[d]      = cvt_tf32(x1 * cs - x2 * sn);
    base[d + 64] = cvt_tf32(x2 * cs + x1 * sn);
}

// ---------------- GEMM: C = A @ W^T, tf32 MMA, cp.async 2-stage ----------------
// MODE 0: A=g_hs, W={g_wq|g_wk|g_wv} by n-block -> g_q/g_k/g_v (V stored tf32)
// MODE 1: A=g_ctx, W=g_wo -> Out (raw fp32)
#define GBK 32
#define GST 36   // 32+4 pad: conflict-free frags, 144B rows (16B-multiple)

template <int MODE>
__global__ __launch_bounds__(256) void gemm_kernel(float* __restrict__ Out) {
    __shared__ __align__(16) float As[2][128][GST];
    __shared__ __align__(16) float Bs[2][128][GST];

    const float* A = (MODE == 0) ? g_hs : g_ctx;

    const int tid  = threadIdx.x;
    const int lane = tid & 31;
    const int warp = tid >> 5;
    const int wm   = warp & 3;
    const int wn   = warp >> 2;
    const int gr   = lane >> 2;
    const int gc   = lane & 3;

    const int bn = blockIdx.x;
    const int m0 = blockIdx.y * 128;

    const float* Bp;
    if (MODE == 0) {
        if (bn < 8)       Bp = g_wq + (size_t)bn * 128 * HIDDEN;
        else if (bn < 10) Bp = g_wk + (size_t)(bn - 8) * 128 * HIDDEN;
        else              Bp = g_wv + (size_t)(bn - 10) * 128 * HIDDEN;
    } else {
        Bp = g_wo + (size_t)bn * 128 * HIDDEN;
    }

    const uint32_t sa = (uint32_t)__cvta_generic_to_shared(&As[0][0][0]);
    const uint32_t sb = (uint32_t)__cvta_generic_to_shared(&Bs[0][0][0]);
    const int ro = tid >> 3;          // 0..31
    const int co = (tid & 7) << 2;    // 0,4,..,28

    auto preload = [&](int it, int stg) {
        const float* Ab = A  + (size_t)m0 * HIDDEN + it * GBK;
        const float* Bb = Bp + it * GBK;
        const uint32_t sao = sa + (uint32_t)(stg * 128 * GST) * 4;
        const uint32_t sbo = sb + (uint32_t)(stg * 128 * GST) * 4;
#pragma unroll
        for (int c = 0; c < 4; c++) {
            const int r = ro + c * 32;
            cp16(sao + (uint32_t)(r * GST + co) * 4, Ab + (size_t)r * HIDDEN + co);
            cp16(sbo + (uint32_t)(r * GST + co) * 4, Bb + (size_t)r * HIDDEN + co);
        }
    };

    float acc[2][8][4];
#pragma unroll
    for (int i = 0; i < 2; i++)
#pragma unroll
        for (int j = 0; j < 8; j++)
#pragma unroll
            for (int r = 0; r < 4; r++) acc[i][j][r] = 0.f;

    preload(0, 0);
    cp_commit();

    const int NIT = HIDDEN / GBK;   // 32
    for (int it = 0; it < NIT; it++) {
        const int cur = it & 1;
        if (it + 1 < NIT) { preload(it + 1, cur ^ 1); cp_commit(); cp_wait<1>(); }
        else              { cp_wait<0>(); }
        __syncthreads();

#pragma unroll
        for (int kk = 0; kk < GBK; kk += 8) {
            uint32_t afr[2][4];
#pragma unroll
            for (int i = 0; i < 2; i++) {
                const int mr = wm * 32 + i * 16;
                afr[i][0] = __float_as_uint(As[cur][mr + gr][kk + gc]);
                afr[i][1] = __float_as_uint(As[cur][mr + gr + 8][kk + gc]);
                afr[i][2] = __float_as_uint(As[cur][mr + gr][kk + gc + 4]);
                afr[i][3] = __float_as_uint(As[cur][mr + gr + 8][kk + gc + 4]);
            }
#pragma unroll
            for (int j = 0; j < 8; j++) {
                const int nr = wn * 64 + j * 8;
                uint32_t bfr[2];
                bfr[0] = __float_as_uint(Bs[cur][nr + gr][kk + gc]);
                bfr[1] = __float_as_uint(Bs[cur][nr + gr][kk + gc + 4]);
#pragma unroll
                for (int i = 0; i < 2; i++) mma_tf32(acc[i][j], afr[i], bfr);
            }
        }
        __syncthreads();
    }

#pragma unroll
    for (int i = 0; i < 2; i++) {
        const int row0 = m0 + wm * 32 + i * 16 + gr;
#pragma unroll
        for (int j = 0; j < 8; j++) {
            const int nl = wn * 64 + j * 8 + gc * 2;
            if (MODE == 0) {
                float* ob;
                bool isv = false;
                if (bn < 8)       ob = g_q + (size_t)bn * SEQ * HD;
                else if (bn < 10) ob = g_k + (size_t)(bn - 8) * SEQ * HD;
                else            { ob = g_v + (size_t)(bn - 10) * SEQ * HD; isv = true; }
                float v0 = acc[i][j][0], v1 = acc[i][j][1], v2 = acc[i][j][2], v3 = acc[i][j][3];
                if (isv) { v0 = cvt_tf32(v0); v1 = cvt_tf32(v1); v2 = cvt_tf32(v2); v3 = cvt_tf32(v3); }
                ob[(size_t)row0 * HD + nl]           = v0;
                ob[(size_t)row0 * HD + nl + 1]       = v1;
                ob[(size_t)(row0 + 8) * HD + nl]     = v2;
                ob[(size_t)(row0 + 8) * HD + nl + 1] = v3;
            } else {
                const int nc = bn * 128 + nl;
                Out[(size_t)row0 * HIDDEN + nc]           = acc[i][j][0];
                Out[(size_t)row0 * HIDDEN + nc + 1]       = acc[i][j][1];
                Out[(size_t)(row0 + 8) * HIDDEN + nc]     = acc[i][j][2];
                Out[(size_t)(row0 + 8) * HIDDEN + nc + 1] = acc[i][j][3];
            }
        }
    }
}

// ---------------- flash attention: AQ=128, 8 warps, cp.async pipelined ----------------
#define AQ 128
#define AKV 64
#define QLD 132
#define KLD 132
#define VLD2 136   // natural [j][d] layout, stride%32==8 -> conflict-free B-frags
#define PLD 68

#define SQ_OFF 0
#define SK0_OFF (AQ * QLD)                 // 16896
#define SK1_OFF (SK0_OFF + AKV * KLD)      // 25344
#define SV_OFF  (SK1_OFF + AKV * KLD)      // 33792
#define SP_OFF  (SV_OFF + AKV * VLD2)      // 42496
#define ATTN_FLOATS (SP_OFF + AQ * PLD)    // 51200
#define ATTN_SMEM (ATTN_FLOATS * 4)        // 204800 B

__global__ __launch_bounds__(256) void attn_kernel() {
    extern __shared__ float sm[];
    float* sQ = sm + SQ_OFF;
    float* sV = sm + SV_OFF;
    float* sP = sm + SP_OFF;
    const uint32_t smb = (uint32_t)__cvta_generic_to_shared(sm);

    const int tid  = threadIdx.x;
    const int lane = tid & 31;
    const int warp = tid >> 5;            // 0..7, rows [warp*16, +16)
    const int gr   = lane >> 2;
    const int gc   = lane & 3;

    const int h  = blockIdx.x & 7;
    const int qi = 31 - (blockIdx.x >> 3);   // heavy tiles first
    const int q0 = qi * AQ;
    const int kv = h >> 2;

    const float* Qg = g_q + ((size_t)h * SEQ + q0) * HD;
    const float* Kg = g_k + (size_t)kv * SEQ * HD;
    const float* Vg = g_v + (size_t)kv * SEQ * HD;

    const int jlow = q0 - WIN + 1;
    const int t0 = (jlow > 0 ? jlow : 0) >> 6;
    const int t1 = (q0 + AQ - 1) >> 6;

    auto kload = [&](int t, int buf) {
        const float* src = Kg + (size_t)(t * 64) * HD;
        const uint32_t base = smb + (uint32_t)(buf ? SK1_OFF : SK0_OFF) * 4;
#pragma unroll
        for (int c = 0; c < 8; c++) {
            const int id = tid + c * 256;      // 0..2047
            const int r  = id >> 5;            // 0..63
            const int ch = (id & 31) << 2;     // 0..124
            cp16(base + (uint32_t)(r * KLD + ch) * 4, src + (size_t)r * HD + ch);
        }
    };
    auto vload = [&](int t) {
        const float* src = Vg + (size_t)(t * 64) * HD;
        const uint32_t base = smb + (uint32_t)SV_OFF * 4;
#pragma unroll
        for (int c = 0; c < 8; c++) {
            const int id = tid + c * 256;
            const int r  = id >> 5;
            const int ch = (id & 31) << 2;
            cp16(base + (uint32_t)(r * VLD2 + ch) * 4, src + (size_t)r * HD + ch);
        }
    };

    kload(t0, 0); cp_commit();
    vload(t0);    cp_commit();

    // stage Q (scaled + tf32) — once per CTA
    const float qscale = 0.08838834764831845f;
#pragma unroll
    for (int c = 0; c < 16; c++) {
        const int idx = tid + c * 256;        // 0..4095
        const int r   = idx >> 5;
        const int c4  = (idx & 31) << 2;
        float4 v = *(const float4*)(Qg + (size_t)r * HD + c4);
        sQ[r * QLD + c4 + 0] = cvt_tf32(v.x * qscale);
        sQ[r * QLD + c4 + 1] = cvt_tf32(v.y * qscale);
        sQ[r * QLD + c4 + 2] = cvt_tf32(v.z * qscale);
        sQ[r * QLD + c4 + 3] = cvt_tf32(v.w * qscale);
    }

    float o[16][4];
#pragma unroll
    for (int n = 0; n < 16; n++)
#pragma unroll
        for (int r = 0; r < 4; r++) o[n][r] = 0.f;
    float mst0 = -1e30f, mst1 = -1e30f;
    float lst0 = 0.f,    lst1 = 0.f;

    const int mr    = warp * 16;
    const int irow0 = q0 + mr + gr;

    for (int t = t0; t <= t1; t++) {
        const int cur = (t - t0) & 1;
        const int j0  = t * 64;

        if (t < t1) { kload(t + 1, cur ^ 1); cp_commit(); cp_wait<2>(); }
        else        { cp_wait<1>(); }
        __syncthreads();

        const float* sK = sm + (cur ? SK1_OFF : SK0_OFF);

        // S = Q K^T
        float sc[8][4];
#pragma unroll
        for (int j = 0; j < 8; j++)
#pragma unroll
            for (int r = 0; r < 4; r++) sc[j][r] = 0.f;

#pragma unroll
        for (int kk = 0; kk < 16; kk++) {
            uint32_t afr[4];
            afr[0] = __float_as_uint(sQ[(mr + gr) * QLD + kk * 8 + gc]);
            afr[1] = __float_as_uint(sQ[(mr + gr + 8) * QLD + kk * 8 + gc]);
            afr[2] = __float_as_uint(sQ[(mr + gr) * QLD + kk * 8 + gc + 4]);
            afr[3] = __float_as_uint(sQ[(mr + gr + 8) * QLD + kk * 8 + gc + 4]);
#pragma unroll
            for (int j = 0; j < 8; j++) {
                uint32_t bfr[2];
                bfr[0] = __float_as_uint(sK[(j * 8 + gr) * KLD + kk * 8 + gc]);
                bfr[1] = __float_as_uint(sK[(j * 8 + gr) * KLD + kk * 8 + gc + 4]);
                mma_tf32(sc[j], afr, bfr);
            }
        }

        // mask: valid = (j <= i) && (j > i - WIN)
#pragma unroll
        for (int j = 0; j < 8; j++) {
            const int jg = j0 + j * 8 + gc * 2;
#pragma unroll
            for (int r = 0; r < 4; r++) {
                const int jc = jg + (r & 1);
                const int ic = irow0 + ((r >> 1) << 3);
                if (jc > ic || jc <= ic - WIN) sc[j][r] = -1e30f;
            }
        }

        // online softmax
        float rm0 = -1e30f, rm1 = -1e30f;
#pragma unroll
        for (int j = 0; j < 8; j++) {
            rm0 = fmaxf(rm0, fmaxf(sc[j][0], sc[j][1]));
            rm1 = fmaxf(rm1, fmaxf(sc[j][2], sc[j][3]));
        }
        rm0 = fmaxf(rm0, __shfl_xor_sync(0xffffffffu, rm0, 1));
        rm0 = fmaxf(rm0, __shfl_xor_sync(0xffffffffu, rm0, 2));
        rm1 = fmaxf(rm1, __shfl_xor_sync(0xffffffffu, rm1, 1));
        rm1 = fmaxf(rm1, __shfl_xor_sync(0xffffffffu, rm1, 2));

        const float mn0 = fmaxf(mst0, rm0);
        const float mn1 = fmaxf(mst1, rm1);
        const float al0 = __expf(mst0 - mn0);
        const float al1 = __expf(mst1 - mn1);
        mst0 = mn0; mst1 = mn1;
        lst0 *= al0; lst1 *= al1;
#pragma unroll
        for (int n = 0; n < 16; n++) {
            o[n][0] *= al0; o[n][1] *= al0;
            o[n][2] *= al1; o[n][3] *= al1;
        }

        float rs0 = 0.f, rs1 = 0.f;
        const int pr0 = (mr + gr) * PLD;
        const int pr1 = (mr + gr + 8) * PLD;
#pragma unroll
        for (int j = 0; j < 8; j++) {
            const float p0 = __expf(sc[j][0] - mn0);
            const float p1 = __expf(sc[j][1] - mn0);
            const float p2 = __expf(sc[j][2] - mn1);
            const float p3 = __expf(sc[j][3] - mn1);
            rs0 += p0 + p1;
            rs1 += p2 + p3;
            const int cb = j * 8 + gc * 2;
            sP[pr0 + cb]     = cvt_tf32(p0);
            sP[pr0 + cb + 1] = cvt_tf32(p1);
            sP[pr1 + cb]     = cvt_tf32(p2);
            sP[pr1 + cb + 1] = cvt_tf32(p3);
        }
        rs0 += __shfl_xor_sync(0xffffffffu, rs0, 1);
        rs0 += __shfl_xor_sync(0xffffffffu, rs0, 2);
        rs1 += __shfl_xor_sync(0xffffffffu, rs1, 1);
        rs1 += __shfl_xor_sync(0xffffffffu, rs1, 2);
        lst0 += rs0; lst1 += rs1;

        __syncwarp();

        if (t < t1) cp_wait<1>(); else cp_wait<0>();
        __syncthreads();   // V visible to all

        // O += P V   (B-frags read natural sV[j][d]: B[n][k]=V[k][n])
#pragma unroll
        for (int kk = 0; kk < 8; kk++) {
            uint32_t afr[4];
            afr[0] = __float_as_uint(sP[(mr + gr) * PLD + kk * 8 + gc]);
            afr[1] = __float_as_uint(sP[(mr + gr + 8) * PLD + kk * 8 + gc]);
            afr[2] = __float_as_uint(sP[(mr + gr) * PLD + kk * 8 + gc + 4]);
            afr[3] = __float_as_uint(sP[(mr + gr + 8) * PLD + kk * 8 + gc + 4]);
#pragma unroll
            for (int n = 0; n < 16; n++) {
                uint32_t bfr[2];
                bfr[0] = __float_as_uint(sV[(kk * 8 + gc) * VLD2 + n * 8 + gr]);
                bfr[1] = __float_as_uint(sV[(kk * 8 + gc + 4) * VLD2 + n * 8 + gr]);
                mma_tf32(o[n], afr, bfr);
            }
        }
        __syncthreads();   // all warps done with sK[cur], sV, sP

        if (t < t1) { vload(t + 1); cp_commit(); }
    }

    const float inv0 = 1.f / lst0;
    const float inv1 = 1.f / lst1;
#pragma unroll
    for (int n = 0; n < 16; n++) {
        const int col = h * HD + n * 8 + gc * 2;
        g_ctx[(size_t)irow0 * HIDDEN + col]           = cvt_tf32(o[n][0] * inv0);
        g_ctx[(size_t)irow0 * HIDDEN + col + 1]       = cvt_tf32(o[n][1] * inv0);
        g_ctx[(size_t)(irow0 + 8) * HIDDEN + col]     = cvt_tf32(o[n][2] * inv1);
        g_ctx[(size_t)(irow0 + 8) * HIDDEN + col + 1] = cvt_tf32(o[n][3] * inv1);
    }
}

// ---------------- launch ----------------
extern "C" void kernel_launch(void* const* d_in, const int* in_sizes, int n_in,
                              void* d_out, int out_size) {
    const float* hs = (const float*)d_in[0];
    const float* wq = (const float*)d_in[1];
    const float* wk = (const float*)d_in[2];
    const float* wv = (const float*)d_in[3];
    const float* wo = (const float*)d_in[4];
    float* out = (float*)d_out;

    cudaFuncSetAttribute(attn_kernel, cudaFuncAttributeMaxDynamicSharedMemorySize, ATTN_SMEM);

    prep_kernel<<<2048, 256>>>(hs, wq, wk, wv, wo);
    rope_table_kernel<<<SEQ, 64>>>();
    gemm_kernel<0><<<dim3(12, 32), 256>>>(nullptr);
    rope_kernel<<<(NH + NKV) * SEQ / 4, 256>>>();
    attn_kernel<<<256, 256, ATTN_SMEM>>>();
    gemm_kernel<1><<<dim3(8, 32), 256>>>(out);
}

// round 7
// speedup vs baseline: 1.9782x; 1.4444x over previous
#include <cuda_runtime.h>
#include <cstdint>

#define HIDDEN 1024
#define NH 8
#define NKV 2
#define HD 128
#define SEQ 4096
#define WIN 2048

// ---------------- device-global scratch ----------------
__device__ float g_q[NH * SEQ * HD];      // [h][s][d]  (tf32 after rope)
__device__ float g_k[NKV * SEQ * HD];     // [kv][s][d] (tf32 after rope)
__device__ float g_v[NKV * SEQ * HD];     // [kv][s][d] (tf32 from gemm0 epilogue)
__device__ float g_ctx[SEQ * HIDDEN];     // [s][h*128+d] (tf32 from attn epilogue)
__device__ float g_hs[SEQ * HIDDEN];      // tf32 copy of hidden_states
__device__ float g_wq[NH * HD * HIDDEN];  // tf32 weights
__device__ float g_wk[NKV * HD * HIDDEN];
__device__ float g_wv[NKV * HD * HIDDEN];
__device__ float g_wo[HIDDEN * NH * HD];
__device__ float g_rcos[SEQ * 64];
__device__ float g_rsin[SEQ * 64];

// ---------------- helpers ----------------
__device__ __forceinline__ float cvt_tf32(float x) {
    uint32_t u;
    asm("cvt.rna.tf32.f32 %0, %1;" : "=r"(u) : "f"(x));
    return __uint_as_float(u);
}

__device__ __forceinline__ void mma_tf32(float* c, const uint32_t* a, const uint32_t* b) {
    asm volatile(
        "mma.sync.aligned.m16n8k8.row.col.f32.tf32.tf32.f32 "
        "{%0,%1,%2,%3}, {%4,%5,%6,%7}, {%8,%9}, {%0,%1,%2,%3};\n"
        : "+f"(c[0]), "+f"(c[1]), "+f"(c[2]), "+f"(c[3])
        : "r"(a[0]), "r"(a[1]), "r"(a[2]), "r"(a[3]), "r"(b[0]), "r"(b[1]));
}

__device__ __forceinline__ void cp16(uint32_t dst, const void* src) {
    asm volatile("cp.async.cg.shared.global [%0], [%1], 16;" :: "r"(dst), "l"(src));
}
__device__ __forceinline__ void cp_commit() { asm volatile("cp.async.commit_group;"); }
template <int N>
__device__ __forceinline__ void cp_wait() { asm volatile("cp.async.wait_group %0;" :: "n"(N)); }

// ---------------- prep: tf32-convert hs + weights ----------------
__global__ void prep_kernel(const float* __restrict__ hs, const float* __restrict__ wq,
                            const float* __restrict__ wk, const float* __restrict__ wv,
                            const float* __restrict__ wo) {
    const int64_t N0 = (int64_t)SEQ * HIDDEN;
    const int64_t N1 = (int64_t)NH * HD * HIDDEN;
    const int64_t N2 = (int64_t)NKV * HD * HIDDEN;
    const int64_t NT = (N0 + N1 + 2 * N2 + N1) >> 2;
    for (int64_t i = blockIdx.x * (int64_t)blockDim.x + threadIdx.x; i < NT;
         i += (int64_t)gridDim.x * blockDim.x) {
        int64_t e = i << 2;
        const float* src; float* dst; int64_t off;
        if (e < N0)                     { src = hs; dst = g_hs; off = e; }
        else if (e < N0 + N1)           { src = wq; dst = g_wq; off = e - N0; }
        else if (e < N0 + N1 + N2)      { src = wk; dst = g_wk; off = e - N0 - N1; }
        else if (e < N0 + N1 + 2 * N2)  { src = wv; dst = g_wv; off = e - N0 - N1 - N2; }
        else                            { src = wo; dst = g_wo; off = e - N0 - N1 - 2 * N2; }
        float4 v = *(const float4*)(src + off);
        v.x = cvt_tf32(v.x); v.y = cvt_tf32(v.y); v.z = cvt_tf32(v.z); v.w = cvt_tf32(v.w);
        *(float4*)(dst + off) = v;
    }
}

// ---------------- rope table ----------------
__global__ void rope_table_kernel() {
    const int s = blockIdx.x;
    const int d = threadIdx.x;
    const float inv = powf(10000.f, -(float)d / 64.f);
    float sn, cs;
    sincosf((float)s * inv, &sn, &cs);
    g_rcos[s * 64 + d] = cs;
    g_rsin[s * 64 + d] = sn;
}

// ---------------- rope (in place, vectorized float4, writes tf32) ----------------
__global__ __launch_bounds__(256) void rope_kernel() {
    const int row = blockIdx.x * 16 + (threadIdx.x >> 4);   // 0 .. 10*SEQ-1
    const int d4  = (threadIdx.x & 15) << 2;                // 0,4,..,60
    float* base;
    if (row < NH * SEQ) base = g_q + (size_t)row * HD;
    else                base = g_k + (size_t)(row - NH * SEQ) * HD;
    const int s = row & (SEQ - 1);
    const float4 cs = *(const float4*)(g_rcos + s * 64 + d4);
    const float4 sn = *(const float4*)(g_rsin + s * 64 + d4);
    const float4 x1 = *(const float4*)(base + d4);
    const float4 x2 = *(const float4*)(base + d4 + 64);
    float4 r1, r2;
    r1.x = cvt_tf32(x1.x * cs.x - x2.x * sn.x); r2.x = cvt_tf32(x2.x * cs.x + x1.x * sn.x);
    r1.y = cvt_tf32(x1.y * cs.y - x2.y * sn.y); r2.y = cvt_tf32(x2.y * cs.y + x1.y * sn.y);
    r1.z = cvt_tf32(x1.z * cs.z - x2.z * sn.z); r2.z = cvt_tf32(x2.z * cs.z + x1.z * sn.z);
    r1.w = cvt_tf32(x1.w * cs.w - x2.w * sn.w); r2.w = cvt_tf32(x2.w * cs.w + x1.w * sn.w);
    *(float4*)(base + d4)      = r1;
    *(float4*)(base + d4 + 64) = r2;
}

// ---------------- GEMM: C = A @ W^T, tf32 MMA, cp.async 2-stage ----------------
#define GBK 32
#define GST 36

template <int MODE>
__global__ __launch_bounds__(256) void gemm_kernel(float* __restrict__ Out) {
    __shared__ __align__(16) float As[2][128][GST];
    __shared__ __align__(16) float Bs[2][128][GST];

    const float* A = (MODE == 0) ? g_hs : g_ctx;

    const int tid  = threadIdx.x;
    const int lane = tid & 31;
    const int warp = tid >> 5;
    const int wm   = warp & 3;
    const int wn   = warp >> 2;
    const int gr   = lane >> 2;
    const int gc   = lane & 3;

    const int bn = blockIdx.x;
    const int m0 = blockIdx.y * 128;

    const float* Bp;
    if (MODE == 0) {
        if (bn < 8)       Bp = g_wq + (size_t)bn * 128 * HIDDEN;
        else if (bn < 10) Bp = g_wk + (size_t)(bn - 8) * 128 * HIDDEN;
        else              Bp = g_wv + (size_t)(bn - 10) * 128 * HIDDEN;
    } else {
        Bp = g_wo + (size_t)bn * 128 * HIDDEN;
    }

    const uint32_t sa = (uint32_t)__cvta_generic_to_shared(&As[0][0][0]);
    const uint32_t sb = (uint32_t)__cvta_generic_to_shared(&Bs[0][0][0]);
    const int ro = tid >> 3;
    const int co = (tid & 7) << 2;

    auto preload = [&](int it, int stg) {
        const float* Ab = A  + (size_t)m0 * HIDDEN + it * GBK;
        const float* Bb = Bp + it * GBK;
        const uint32_t sao = sa + (uint32_t)(stg * 128 * GST) * 4;
        const uint32_t sbo = sb + (uint32_t)(stg * 128 * GST) * 4;
#pragma unroll
        for (int c = 0; c < 4; c++) {
            const int r = ro + c * 32;
            cp16(sao + (uint32_t)(r * GST + co) * 4, Ab + (size_t)r * HIDDEN + co);
            cp16(sbo + (uint32_t)(r * GST + co) * 4, Bb + (size_t)r * HIDDEN + co);
        }
    };

    float acc[2][8][4];
#pragma unroll
    for (int i = 0; i < 2; i++)
#pragma unroll
        for (int j = 0; j < 8; j++)
#pragma unroll
            for (int r = 0; r < 4; r++) acc[i][j][r] = 0.f;

    preload(0, 0);
    cp_commit();

    const int NIT = HIDDEN / GBK;
    for (int it = 0; it < NIT; it++) {
        const int cur = it & 1;
        if (it + 1 < NIT) { preload(it + 1, cur ^ 1); cp_commit(); cp_wait<1>(); }
        else              { cp_wait<0>(); }
        __syncthreads();

#pragma unroll
        for (int kk = 0; kk < GBK; kk += 8) {
            uint32_t afr[2][4];
#pragma unroll
            for (int i = 0; i < 2; i++) {
                const int mr = wm * 32 + i * 16;
                afr[i][0] = __float_as_uint(As[cur][mr + gr][kk + gc]);
                afr[i][1] = __float_as_uint(As[cur][mr + gr + 8][kk + gc]);
                afr[i][2] = __float_as_uint(As[cur][mr + gr][kk + gc + 4]);
                afr[i][3] = __float_as_uint(As[cur][mr + gr + 8][kk + gc + 4]);
            }
#pragma unroll
            for (int j = 0; j < 8; j++) {
                const int nr = wn * 64 + j * 8;
                uint32_t bfr[2];
                bfr[0] = __float_as_uint(Bs[cur][nr + gr][kk + gc]);
                bfr[1] = __float_as_uint(Bs[cur][nr + gr][kk + gc + 4]);
#pragma unroll
                for (int i = 0; i < 2; i++) mma_tf32(acc[i][j], afr[i], bfr);
            }
        }
        __syncthreads();
    }

#pragma unroll
    for (int i = 0; i < 2; i++) {
        const int row0 = m0 + wm * 32 + i * 16 + gr;
#pragma unroll
        for (int j = 0; j < 8; j++) {
            const int nl = wn * 64 + j * 8 + gc * 2;
            if (MODE == 0) {
                float* ob;
                bool isv = false;
                if (bn < 8)       ob = g_q + (size_t)bn * SEQ * HD;
                else if (bn < 10) ob = g_k + (size_t)(bn - 8) * SEQ * HD;
                else            { ob = g_v + (size_t)(bn - 10) * SEQ * HD; isv = true; }
                float v0 = acc[i][j][0], v1 = acc[i][j][1], v2 = acc[i][j][2], v3 = acc[i][j][3];
                if (isv) { v0 = cvt_tf32(v0); v1 = cvt_tf32(v1); v2 = cvt_tf32(v2); v3 = cvt_tf32(v3); }
                ob[(size_t)row0 * HD + nl]           = v0;
                ob[(size_t)row0 * HD + nl + 1]       = v1;
                ob[(size_t)(row0 + 8) * HD + nl]     = v2;
                ob[(size_t)(row0 + 8) * HD + nl + 1] = v3;
            } else {
                const int nc = bn * 128 + nl;
                Out[(size_t)row0 * HIDDEN + nc]           = acc[i][j][0];
                Out[(size_t)row0 * HIDDEN + nc + 1]       = acc[i][j][1];
                Out[(size_t)(row0 + 8) * HIDDEN + nc]     = acc[i][j][2];
                Out[(size_t)(row0 + 8) * HIDDEN + nc + 1] = acc[i][j][3];
            }
        }
    }
}

// ---------------- flash attention: AQ=64 x AKV=32, 4 warps, 2 CTAs/SM ----------------
#define AQ 64
#define AKV 32
#define QLD 132
#define KLD 132
#define VLD 132
#define PLD 36

#define SQ_OFF 0
#define SK0_OFF (AQ * QLD)                  // 8448
#define SK1_OFF (SK0_OFF + AKV * KLD)       // 12672
#define SV_OFF  (SK1_OFF + AKV * KLD)       // 16896
#define SP_OFF  (SV_OFF + AKV * VLD)        // 21120
#define ATTN_FLOATS (SP_OFF + AQ * PLD)     // 23424
#define ATTN_SMEM (ATTN_FLOATS * 4)         // 93696 B -> 2 CTAs/SM

__global__ __launch_bounds__(128) void attn_kernel() {
    extern __shared__ float sm[];
    float* sQ = sm + SQ_OFF;
    float* sV = sm + SV_OFF;
    float* sP = sm + SP_OFF;
    const uint32_t smb = (uint32_t)__cvta_generic_to_shared(sm);

    const int tid  = threadIdx.x;
    const int lane = tid & 31;
    const int warp = tid >> 5;            // 0..3, rows [warp*16, +16)
    const int gr   = lane >> 2;
    const int gc   = lane & 3;

    const int h  = blockIdx.x & 7;
    const int qi = 63 - (blockIdx.x >> 3);   // heavy tiles first
    const int q0 = qi * AQ;
    const int kv = h >> 2;

    const float* Qg = g_q + ((size_t)h * SEQ + q0) * HD;
    const float* Kg = g_k + (size_t)kv * SEQ * HD;
    const float* Vg = g_v + (size_t)kv * SEQ * HD;

    const int jlow = q0 - WIN + 1;
    const int t0 = (jlow > 0 ? jlow : 0) >> 5;
    const int t1 = (q0 + AQ - 1) >> 5;

    auto kload = [&](int t, int buf) {
        const float* src = Kg + (size_t)(t * AKV) * HD;
        const uint32_t base = smb + (uint32_t)(buf ? SK1_OFF : SK0_OFF) * 4;
#pragma unroll
        for (int c = 0; c < 8; c++) {
            const int id = tid + c * 128;      // 0..1023
            const int r  = id >> 5;            // 0..31
            const int ch = (id & 31) << 2;
            cp16(base + (uint32_t)(r * KLD + ch) * 4, src + (size_t)r * HD + ch);
        }
    };
    auto vload = [&](int t) {
        const float* src = Vg + (size_t)(t * AKV) * HD;
        const uint32_t base = smb + (uint32_t)SV_OFF * 4;
#pragma unroll
        for (int c = 0; c < 8; c++) {
            const int id = tid + c * 128;
            const int r  = id >> 5;
            const int ch = (id & 31) << 2;
            cp16(base + (uint32_t)(r * VLD + ch) * 4, src + (size_t)r * HD + ch);
        }
    };

    kload(t0, 0); cp_commit();
    vload(t0);    cp_commit();

    // stage Q (scaled + tf32) — once per CTA
    const float qscale = 0.08838834764831845f;
#pragma unroll
    for (int c = 0; c < 16; c++) {
        const int idx = tid + c * 128;        // 0..2047
        const int r   = idx >> 5;             // 0..63
        const int c4  = (idx & 31) << 2;
        float4 v = *(const float4*)(Qg + (size_t)r * HD + c4);
        sQ[r * QLD + c4 + 0] = cvt_tf32(v.x * qscale);
        sQ[r * QLD + c4 + 1] = cvt_tf32(v.y * qscale);
        sQ[r * QLD + c4 + 2] = cvt_tf32(v.z * qscale);
        sQ[r * QLD + c4 + 3] = cvt_tf32(v.w * qscale);
    }

    float o[16][4];
#pragma unroll
    for (int n = 0; n < 16; n++)
#pragma unroll
        for (int r = 0; r < 4; r++) o[n][r] = 0.f;
    float mst0 = -1e30f, mst1 = -1e30f;
    float lst0 = 0.f,    lst1 = 0.f;

    const int mr    = warp * 16;
    const int irow0 = q0 + mr + gr;

    for (int t = t0; t <= t1; t++) {
        const int cur = (t - t0) & 1;
        const int j0  = t * AKV;

        if (t < t1) { kload(t + 1, cur ^ 1); cp_commit(); cp_wait<2>(); }
        else        { cp_wait<1>(); }
        __syncthreads();

        const float* sK = sm + (cur ? SK1_OFF : SK0_OFF);

        // S = Q K^T   (64q x 32k)
        float sc[4][4];
#pragma unroll
        for (int j = 0; j < 4; j++)
#pragma unroll
            for (int r = 0; r < 4; r++) sc[j][r] = 0.f;

#pragma unroll
        for (int kk = 0; kk < 16; kk++) {
            uint32_t afr[4];
            afr[0] = __float_as_uint(sQ[(mr + gr) * QLD + kk * 8 + gc]);
            afr[1] = __float_as_uint(sQ[(mr + gr + 8) * QLD + kk * 8 + gc]);
            afr[2] = __float_as_uint(sQ[(mr + gr) * QLD + kk * 8 + gc + 4]);
            afr[3] = __float_as_uint(sQ[(mr + gr + 8) * QLD + kk * 8 + gc + 4]);
#pragma unroll
            for (int j = 0; j < 4; j++) {
                uint32_t bfr[2];
                bfr[0] = __float_as_uint(sK[(j * 8 + gr) * KLD + kk * 8 + gc]);
                bfr[1] = __float_as_uint(sK[(j * 8 + gr) * KLD + kk * 8 + gc + 4]);
                mma_tf32(sc[j], afr, bfr);
            }
        }

        // mask: valid = (j <= i) && (j > i - WIN)
#pragma unroll
        for (int j = 0; j < 4; j++) {
            const int jg = j0 + j * 8 + gc * 2;
#pragma unroll
            for (int r = 0; r < 4; r++) {
                const int jc = jg + (r & 1);
                const int ic = irow0 + ((r >> 1) << 3);
                if (jc > ic || jc <= ic - WIN) sc[j][r] = -1e30f;
            }
        }

        // online softmax
        float rm0 = -1e30f, rm1 = -1e30f;
#pragma unroll
        for (int j = 0; j < 4; j++) {
            rm0 = fmaxf(rm0, fmaxf(sc[j][0], sc[j][1]));
            rm1 = fmaxf(rm1, fmaxf(sc[j][2], sc[j][3]));
        }
        rm0 = fmaxf(rm0, __shfl_xor_sync(0xffffffffu, rm0, 1));
        rm0 = fmaxf(rm0, __shfl_xor_sync(0xffffffffu, rm0, 2));
        rm1 = fmaxf(rm1, __shfl_xor_sync(0xffffffffu, rm1, 1));
        rm1 = fmaxf(rm1, __shfl_xor_sync(0xffffffffu, rm1, 2));

        const float mn0 = fmaxf(mst0, rm0);
        const float mn1 = fmaxf(mst1, rm1);
        const float al0 = __expf(mst0 - mn0);
        const float al1 = __expf(mst1 - mn1);
        mst0 = mn0; mst1 = mn1;
        lst0 *= al0; lst1 *= al1;
#pragma unroll
        for (int n = 0; n < 16; n++) {
            o[n][0] *= al0; o[n][1] *= al0;
            o[n][2] *= al1; o[n][3] *= al1;
        }

        float rs0 = 0.f, rs1 = 0.f;
        const int pr0 = (mr + gr) * PLD;
        const int pr1 = (mr + gr + 8) * PLD;
#pragma unroll
        for (int j = 0; j < 4; j++) {
            const float p0 = __expf(sc[j][0] - mn0);
            const float p1 = __expf(sc[j][1] - mn0);
            const float p2 = __expf(sc[j][2] - mn1);
            const float p3 = __expf(sc[j][3] - mn1);
            rs0 += p0 + p1;
            rs1 += p2 + p3;
            const int cb = j * 8 + gc * 2;
            sP[pr0 + cb]     = cvt_tf32(p0);
            sP[pr0 + cb + 1] = cvt_tf32(p1);
            sP[pr1 + cb]     = cvt_tf32(p2);
            sP[pr1 + cb + 1] = cvt_tf32(p3);
        }
        rs0 += __shfl_xor_sync(0xffffffffu, rs0, 1);
        rs0 += __shfl_xor_sync(0xffffffffu, rs0, 2);
        rs1 += __shfl_xor_sync(0xffffffffu, rs1, 1);
        rs1 += __shfl_xor_sync(0xffffffffu, rs1, 2);
        lst0 += rs0; lst1 += rs1;

        __syncwarp();

        if (t < t1) cp_wait<1>(); else cp_wait<0>();
        __syncthreads();   // V visible to all

        // O += P V
#pragma unroll
        for (int kk = 0; kk < 4; kk++) {
            uint32_t afr[4];
            afr[0] = __float_as_uint(sP[(mr + gr) * PLD + kk * 8 + gc]);
            afr[1] = __float_as_uint(sP[(mr + gr + 8) * PLD + kk * 8 + gc]);
            afr[2] = __float_as_uint(sP[(mr + gr) * PLD + kk * 8 + gc + 4]);
            afr[3] = __float_as_uint(sP[(mr + gr + 8) * PLD + kk * 8 + gc + 4]);
#pragma unroll
            for (int n = 0; n < 16; n++) {
                uint32_t bfr[2];
                bfr[0] = __float_as_uint(sV[(kk * 8 + gc) * VLD + n * 8 + gr]);
                bfr[1] = __float_as_uint(sV[(kk * 8 + gc + 4) * VLD + n * 8 + gr]);
                mma_tf32(o[n], afr, bfr);
            }
        }
        __syncthreads();   // all warps done with sV/sP before next vload

        if (t < t1) { vload(t + 1); cp_commit(); }
    }

    const float inv0 = 1.f / lst0;
    const float inv1 = 1.f / lst1;
#pragma unroll
    for (int n = 0; n < 16; n++) {
        const int col = h * HD + n * 8 + gc * 2;
        g_ctx[(size_t)irow0 * HIDDEN + col]           = cvt_tf32(o[n][0] * inv0);
        g_ctx[(size_t)irow0 * HIDDEN + col + 1]       = cvt_tf32(o[n][1] * inv0);
        g_ctx[(size_t)(irow0 + 8) * HIDDEN + col]     = cvt_tf32(o[n][2] * inv1);
        g_ctx[(size_t)(irow0 + 8) * HIDDEN + col + 1] = cvt_tf32(o[n][3] * inv1);
    }
}

// ---------------- launch ----------------
extern "C" void kernel_launch(void* const* d_in, const int* in_sizes, int n_in,
                              void* d_out, int out_size) {
    const float* hs = (const float*)d_in[0];
    const float* wq = (const float*)d_in[1];
    const float* wk = (const float*)d_in[2];
    const float* wv = (const float*)d_in[3];
    const float* wo = (const float*)d_in[4];
    float* out = (float*)d_out;

    cudaFuncSetAttribute(attn_kernel, cudaFuncAttributeMaxDynamicSharedMemorySize, ATTN_SMEM);

    prep_kernel<<<2048, 256>>>(hs, wq, wk, wv, wo);
    rope_table_kernel<<<SEQ, 64>>>();
    gemm_kernel<0><<<dim3(12, 32), 256>>>(nullptr);
    rope_kernel<<<(NH + NKV) * SEQ / 16, 256>>>();
    attn_kernel<<<512, 128, ATTN_SMEM>>>();
    gemm_kernel<1><<<dim3(8, 32), 256>>>(out);
}

// round 8
// speedup vs baseline: 2.1131x; 1.0682x over previous
#include <cuda_runtime.h>
#include <cstdint>

#define HIDDEN 1024
#define NH 8
#define NKV 2
#define HD 128
#define SEQ 4096
#define WIN 2048

// ---------------- device-global scratch ----------------
__device__ float g_q[NH * SEQ * HD];      // [h][s][d]  (tf32 after rope)
__device__ float g_k[NKV * SEQ * HD];     // [kv][s][d] (tf32 after rope)
__device__ float g_v[NKV * SEQ * HD];     // [kv][s][d] (tf32 from gemm0 epilogue)
__device__ float g_ctx[SEQ * HIDDEN];     // [s][h*128+d] (tf32 from attn epilogue)
__device__ float g_hs[SEQ * HIDDEN];      // tf32 copy of hidden_states
__device__ float g_wq[NH * HD * HIDDEN];  // tf32 weights
__device__ float g_wk[NKV * HD * HIDDEN];
__device__ float g_wv[NKV * HD * HIDDEN];
__device__ float g_wo[HIDDEN * NH * HD];
__device__ float g_rcos[SEQ * 64];
__device__ float g_rsin[SEQ * 64];

// ---------------- helpers ----------------
__device__ __forceinline__ float cvt_tf32(float x) {
    uint32_t u;
    asm("cvt.rna.tf32.f32 %0, %1;" : "=r"(u) : "f"(x));
    return __uint_as_float(u);
}

__device__ __forceinline__ void mma_tf32(float* c, const uint32_t* a, const uint32_t* b) {
    asm volatile(
        "mma.sync.aligned.m16n8k8.row.col.f32.tf32.tf32.f32 "
        "{%0,%1,%2,%3}, {%4,%5,%6,%7}, {%8,%9}, {%0,%1,%2,%3};\n"
        : "+f"(c[0]), "+f"(c[1]), "+f"(c[2]), "+f"(c[3])
        : "r"(a[0]), "r"(a[1]), "r"(a[2]), "r"(a[3]), "r"(b[0]), "r"(b[1]));
}

__device__ __forceinline__ void cp16(uint32_t dst, const void* src) {
    asm volatile("cp.async.cg.shared.global [%0], [%1], 16;" :: "r"(dst), "l"(src));
}
__device__ __forceinline__ void cp_commit() { asm volatile("cp.async.commit_group;"); }
template <int N>
__device__ __forceinline__ void cp_wait() { asm volatile("cp.async.wait_group %0;" :: "n"(N)); }

// ---------------- prep: tf32-convert hs + weights (int32 indexing) ----------------
__global__ void prep_kernel(const float* __restrict__ hs, const float* __restrict__ wq,
                            const float* __restrict__ wk, const float* __restrict__ wv,
                            const float* __restrict__ wo) {
    const int N0 = SEQ * HIDDEN;            // 4M
    const int N1 = NH * HD * HIDDEN;        // 1M
    const int N2 = NKV * HD * HIDDEN;       // 256K
    const int NT = (N0 + N1 + 2 * N2 + N1) >> 2;
    for (int i = blockIdx.x * blockDim.x + threadIdx.x; i < NT;
         i += gridDim.x * blockDim.x) {
        int e = i << 2;
        const float* src; float* dst; int off;
        if (e < N0)                     { src = hs; dst = g_hs; off = e; }
        else if (e < N0 + N1)           { src = wq; dst = g_wq; off = e - N0; }
        else if (e < N0 + N1 + N2)      { src = wk; dst = g_wk; off = e - N0 - N1; }
        else if (e < N0 + N1 + 2 * N2)  { src = wv; dst = g_wv; off = e - N0 - N1 - N2; }
        else                            { src = wo; dst = g_wo; off = e - N0 - N1 - 2 * N2; }
        float4 v = *(const float4*)(src + off);
        v.x = cvt_tf32(v.x); v.y = cvt_tf32(v.y); v.z = cvt_tf32(v.z); v.w = cvt_tf32(v.w);
        *(float4*)(dst + off) = v;
    }
}

// ---------------- rope table ----------------
__global__ void rope_table_kernel() {
    const int s = blockIdx.x;
    const int d = threadIdx.x;
    const float inv = powf(10000.f, -(float)d / 64.f);
    float sn, cs;
    sincosf((float)s * inv, &sn, &cs);
    g_rcos[s * 64 + d] = cs;
    g_rsin[s * 64 + d] = sn;
}

// ---------------- rope (in place, vectorized float4, writes tf32) ----------------
__global__ __launch_bounds__(256) void rope_kernel() {
    const int row = blockIdx.x * 16 + (threadIdx.x >> 4);
    const int d4  = (threadIdx.x & 15) << 2;
    float* base;
    if (row < NH * SEQ) base = g_q + (size_t)row * HD;
    else                base = g_k + (size_t)(row - NH * SEQ) * HD;
    const int s = row & (SEQ - 1);
    const float4 cs = *(const float4*)(g_rcos + s * 64 + d4);
    const float4 sn = *(const float4*)(g_rsin + s * 64 + d4);
    const float4 x1 = *(const float4*)(base + d4);
    const float4 x2 = *(const float4*)(base + d4 + 64);
    float4 r1, r2;
    r1.x = cvt_tf32(x1.x * cs.x - x2.x * sn.x); r2.x = cvt_tf32(x2.x * cs.x + x1.x * sn.x);
    r1.y = cvt_tf32(x1.y * cs.y - x2.y * sn.y); r2.y = cvt_tf32(x2.y * cs.y + x1.y * sn.y);
    r1.z = cvt_tf32(x1.z * cs.z - x2.z * sn.z); r2.z = cvt_tf32(x2.z * cs.z + x1.z * sn.z);
    r1.w = cvt_tf32(x1.w * cs.w - x2.w * sn.w); r2.w = cvt_tf32(x2.w * cs.w + x1.w * sn.w);
    *(float4*)(base + d4)      = r1;
    *(float4*)(base + d4 + 64) = r2;
}

// ---------------- GEMM: C = A @ W^T, tf32 MMA, cp.async 2-stage ----------------
#define GBK 32
#define GST 36

template <int MODE>
__global__ __launch_bounds__(256) void gemm_kernel(float* __restrict__ Out) {
    __shared__ __align__(16) float As[2][128][GST];
    __shared__ __align__(16) float Bs[2][128][GST];

    const float* A = (MODE == 0) ? g_hs : g_ctx;

    const int tid  = threadIdx.x;
    const int lane = tid & 31;
    const int warp = tid >> 5;
    const int wm   = warp & 3;
    const int wn   = warp >> 2;
    const int gr   = lane >> 2;
    const int gc   = lane & 3;

    const int bn = blockIdx.x;
    const int m0 = blockIdx.y * 128;

    const float* Bp;
    if (MODE == 0) {
        if (bn < 8)       Bp = g_wq + (size_t)bn * 128 * HIDDEN;
        else if (bn < 10) Bp = g_wk + (size_t)(bn - 8) * 128 * HIDDEN;
        else              Bp = g_wv + (size_t)(bn - 10) * 128 * HIDDEN;
    } else {
        Bp = g_wo + (size_t)bn * 128 * HIDDEN;
    }

    const uint32_t sa = (uint32_t)__cvta_generic_to_shared(&As[0][0][0]);
    const uint32_t sb = (uint32_t)__cvta_generic_to_shared(&Bs[0][0][0]);
    const int ro = tid >> 3;
    const int co = (tid & 7) << 2;

    auto preload = [&](int it, int stg) {
        const float* Ab = A  + (size_t)m0 * HIDDEN + it * GBK;
        const float* Bb = Bp + it * GBK;
        const uint32_t sao = sa + (uint32_t)(stg * 128 * GST) * 4;
        const uint32_t sbo = sb + (uint32_t)(stg * 128 * GST) * 4;
#pragma unroll
        for (int c = 0; c < 4; c++) {
            const int r = ro + c * 32;
            cp16(sao + (uint32_t)(r * GST + co) * 4, Ab + (size_t)r * HIDDEN + co);
            cp16(sbo + (uint32_t)(r * GST + co) * 4, Bb + (size_t)r * HIDDEN + co);
        }
    };

    float acc[2][8][4];
#pragma unroll
    for (int i = 0; i < 2; i++)
#pragma unroll
        for (int j = 0; j < 8; j++)
#pragma unroll
            for (int r = 0; r < 4; r++) acc[i][j][r] = 0.f;

    preload(0, 0);
    cp_commit();

    const int NIT = HIDDEN / GBK;
    for (int it = 0; it < NIT; it++) {
        const int cur = it & 1;
        if (it + 1 < NIT) { preload(it + 1, cur ^ 1); cp_commit(); cp_wait<1>(); }
        else              { cp_wait<0>(); }
        __syncthreads();

#pragma unroll
        for (int kk = 0; kk < GBK; kk += 8) {
            uint32_t afr[2][4];
#pragma unroll
            for (int i = 0; i < 2; i++) {
                const int mr = wm * 32 + i * 16;
                afr[i][0] = __float_as_uint(As[cur][mr + gr][kk + gc]);
                afr[i][1] = __float_as_uint(As[cur][mr + gr + 8][kk + gc]);
                afr[i][2] = __float_as_uint(As[cur][mr + gr][kk + gc + 4]);
                afr[i][3] = __float_as_uint(As[cur][mr + gr + 8][kk + gc + 4]);
            }
#pragma unroll
            for (int j = 0; j < 8; j++) {
                const int nr = wn * 64 + j * 8;
                uint32_t bfr[2];
                bfr[0] = __float_as_uint(Bs[cur][nr + gr][kk + gc]);
                bfr[1] = __float_as_uint(Bs[cur][nr + gr][kk + gc + 4]);
#pragma unroll
                for (int i = 0; i < 2; i++) mma_tf32(acc[i][j], afr[i], bfr);
            }
        }
        __syncthreads();
    }

#pragma unroll
    for (int i = 0; i < 2; i++) {
        const int row0 = m0 + wm * 32 + i * 16 + gr;
#pragma unroll
        for (int j = 0; j < 8; j++) {
            const int nl = wn * 64 + j * 8 + gc * 2;
            if (MODE == 0) {
                float* ob;
                bool isv = false;
                if (bn < 8)       ob = g_q + (size_t)bn * SEQ * HD;
                else if (bn < 10) ob = g_k + (size_t)(bn - 8) * SEQ * HD;
                else            { ob = g_v + (size_t)(bn - 10) * SEQ * HD; isv = true; }
                float v0 = acc[i][j][0], v1 = acc[i][j][1], v2 = acc[i][j][2], v3 = acc[i][j][3];
                if (isv) { v0 = cvt_tf32(v0); v1 = cvt_tf32(v1); v2 = cvt_tf32(v2); v3 = cvt_tf32(v3); }
                ob[(size_t)row0 * HD + nl]           = v0;
                ob[(size_t)row0 * HD + nl + 1]       = v1;
                ob[(size_t)(row0 + 8) * HD + nl]     = v2;
                ob[(size_t)(row0 + 8) * HD + nl + 1] = v3;
            } else {
                const int nc = bn * 128 + nl;
                Out[(size_t)row0 * HIDDEN + nc]           = acc[i][j][0];
                Out[(size_t)row0 * HIDDEN + nc + 1]       = acc[i][j][1];
                Out[(size_t)(row0 + 8) * HIDDEN + nc]     = acc[i][j][2];
                Out[(size_t)(row0 + 8) * HIDDEN + nc + 1] = acc[i][j][3];
            }
        }
    }
}

// ---------------- flash attention: AQ=64 x AKV=32, Q-in-regs, P-via-shfl ----------------
#define AQ 64
#define AKV 32
#define KLD 132   // conflict-free: lane bank = 4*gr+gc
#define VLD 136   // conflict-free: lane bank = 8*gc+gr

#define SK0_OFF 0
#define SK1_OFF (AKV * KLD)                 // 4224
#define SV0_OFF (2 * AKV * KLD)             // 8448
#define SV1_OFF (SV0_OFF + AKV * VLD)       // 12800
#define ATTN_FLOATS (SV1_OFF + AKV * VLD)   // 17152
#define ATTN_SMEM (ATTN_FLOATS * 4)         // 68608 B -> 2 CTAs/SM

__global__ __launch_bounds__(128) void attn_kernel() {
    extern __shared__ float sm[];
    const uint32_t smb = (uint32_t)__cvta_generic_to_shared(sm);

    const int tid  = threadIdx.x;
    const int lane = tid & 31;
    const int warp = tid >> 5;            // 0..3, rows [warp*16, +16)
    const int gr   = lane >> 2;
    const int gc   = lane & 3;

    const int h  = blockIdx.x & 7;
    const int qi = 63 - (blockIdx.x >> 3);   // heavy tiles first
    const int q0 = qi * AQ;
    const int kv = h >> 2;

    const float* Qg = g_q + ((size_t)h * SEQ + q0) * HD;
    const float* Kg = g_k + (size_t)kv * SEQ * HD;
    const float* Vg = g_v + (size_t)kv * SEQ * HD;

    const int jlow = q0 - WIN + 1;
    const int t0 = (jlow > 0 ? jlow : 0) >> 5;
    const int t1 = (q0 + AQ - 1) >> 5;

    auto kload = [&](int t, int buf) {
        const float* src = Kg + (size_t)(t * AKV) * HD;
        const uint32_t base = smb + (uint32_t)(buf ? SK1_OFF : SK0_OFF) * 4;
#pragma unroll
        for (int c = 0; c < 8; c++) {
            const int id = tid + c * 128;
            const int r  = id >> 5;
            const int ch = (id & 31) << 2;
            cp16(base + (uint32_t)(r * KLD + ch) * 4, src + (size_t)r * HD + ch);
        }
    };
    auto vload = [&](int t, int buf) {
        const float* src = Vg + (size_t)(t * AKV) * HD;
        const uint32_t base = smb + (uint32_t)(buf ? SV1_OFF : SV0_OFF) * 4;
#pragma unroll
        for (int c = 0; c < 8; c++) {
            const int id = tid + c * 128;
            const int r  = id >> 5;
            const int ch = (id & 31) << 2;
            cp16(base + (uint32_t)(r * VLD + ch) * 4, src + (size_t)r * HD + ch);
        }
    };

    // ---- stage Q (scaled + tf32) through the K-buffer region, then lift to regs ----
    const float qscale = 0.08838834764831845f;
#pragma unroll
    for (int c = 0; c < 16; c++) {
        const int idx = tid + c * 128;        // 0..2047
        const int r   = idx >> 5;             // 0..63
        const int c4  = (idx & 31) << 2;
        float4 v = *(const float4*)(Qg + (size_t)r * HD + c4);
        sm[r * KLD + c4 + 0] = cvt_tf32(v.x * qscale);
        sm[r * KLD + c4 + 1] = cvt_tf32(v.y * qscale);
        sm[r * KLD + c4 + 2] = cvt_tf32(v.z * qscale);
        sm[r * KLD + c4 + 3] = cvt_tf32(v.w * qscale);
    }
    __syncthreads();

    const int mr = warp * 16;
    uint32_t qf[16][4];
#pragma unroll
    for (int kk = 0; kk < 16; kk++) {
        qf[kk][0] = __float_as_uint(sm[(mr + gr) * KLD + kk * 8 + gc]);
        qf[kk][1] = __float_as_uint(sm[(mr + gr + 8) * KLD + kk * 8 + gc]);
        qf[kk][2] = __float_as_uint(sm[(mr + gr) * KLD + kk * 8 + gc + 4]);
        qf[kk][3] = __float_as_uint(sm[(mr + gr + 8) * KLD + kk * 8 + gc + 4]);
    }
    __syncthreads();

    kload(t0, 0); vload(t0, 0); cp_commit();

    float o[16][4];
#pragma unroll
    for (int n = 0; n < 16; n++)
#pragma unroll
        for (int r = 0; r < 4; r++) o[n][r] = 0.f;
    float mst0 = -1e30f, mst1 = -1e30f;
    float lst0 = 0.f,    lst1 = 0.f;

    const int irow0 = q0 + mr + gr;
    const int psrc0 = (lane & ~3) | (gc >> 1);     // shfl source for a0/a1
    const int psrc1 = psrc0 + 2;                   // shfl source for a2/a3
    const bool podd = (gc & 1);

    for (int t = t0; t <= t1; t++) {
        const int cur = (t - t0) & 1;
        const int j0  = t * AKV;

        if (t < t1) { kload(t + 1, cur ^ 1); vload(t + 1, cur ^ 1); cp_commit(); cp_wait<1>(); }
        else        { cp_wait<0>(); }
        __syncthreads();   // buffers[cur] filled & visible to all warps

        const float* sK = sm + (cur ? SK1_OFF : SK0_OFF);
        const float* sV = sm + (cur ? SV1_OFF : SV0_OFF);

        // S = Q K^T   (64q x 32k), Q from registers
        float sc[4][4];
#pragma unroll
        for (int j = 0; j < 4; j++)
#pragma unroll
            for (int r = 0; r < 4; r++) sc[j][r] = 0.f;

#pragma unroll
        for (int kk = 0; kk < 16; kk++) {
#pragma unroll
            for (int j = 0; j < 4; j++) {
                uint32_t bfr[2];
                bfr[0] = __float_as_uint(sK[(j * 8 + gr) * KLD + kk * 8 + gc]);
                bfr[1] = __float_as_uint(sK[(j * 8 + gr) * KLD + kk * 8 + gc + 4]);
                mma_tf32(sc[j], qf[kk], bfr);
            }
        }

        // mask: valid = (j <= i) && (j > i - WIN)
#pragma unroll
        for (int j = 0; j < 4; j++) {
            const int jg = j0 + j * 8 + gc * 2;
#pragma unroll
            for (int r = 0; r < 4; r++) {
                const int jc = jg + (r & 1);
                const int ic = irow0 + ((r >> 1) << 3);
                if (jc > ic || jc <= ic - WIN) sc[j][r] = -1e30f;
            }
        }

        // online softmax
        float rm0 = -1e30f, rm1 = -1e30f;
#pragma unroll
        for (int j = 0; j < 4; j++) {
            rm0 = fmaxf(rm0, fmaxf(sc[j][0], sc[j][1]));
            rm1 = fmaxf(rm1, fmaxf(sc[j][2], sc[j][3]));
        }
        rm0 = fmaxf(rm0, __shfl_xor_sync(0xffffffffu, rm0, 1));
        rm0 = fmaxf(rm0, __shfl_xor_sync(0xffffffffu, rm0, 2));
        rm1 = fmaxf(rm1, __shfl_xor_sync(0xffffffffu, rm1, 1));
        rm1 = fmaxf(rm1, __shfl_xor_sync(0xffffffffu, rm1, 2));

        const float mn0 = fmaxf(mst0, rm0);
        const float mn1 = fmaxf(mst1, rm1);
        const float al0 = __expf(mst0 - mn0);
        const float al1 = __expf(mst1 - mn1);
        mst0 = mn0; mst1 = mn1;
        lst0 *= al0; lst1 *= al1;
#pragma unroll
        for (int n = 0; n < 16; n++) {
            o[n][0] *= al0; o[n][1] *= al0;
            o[n][2] *= al1; o[n][3] *= al1;
        }

        // exp + row sums; keep P in registers (C-layout)
        float rs0 = 0.f, rs1 = 0.f;
        float p[4][4];
#pragma unroll
        for (int j = 0; j < 4; j++) {
            p[j][0] = cvt_tf32(__expf(sc[j][0] - mn0));
            p[j][1] = cvt_tf32(__expf(sc[j][1] - mn0));
            p[j][2] = cvt_tf32(__expf(sc[j][2] - mn1));
            p[j][3] = cvt_tf32(__expf(sc[j][3] - mn1));
            rs0 += p[j][0] + p[j][1];
            rs1 += p[j][2] + p[j][3];
        }
        rs0 += __shfl_xor_sync(0xffffffffu, rs0, 1);
        rs0 += __shfl_xor_sync(0xffffffffu, rs0, 2);
        rs1 += __shfl_xor_sync(0xffffffffu, rs1, 1);
        rs1 += __shfl_xor_sync(0xffffffffu, rs1, 2);
        lst0 += rs0; lst1 += rs1;

        // C-layout -> A-layout fragment conversion via shuffles:
        // a-frag k=q of tile j lives in lane (gr, q>>1), reg parity q&1.
        uint32_t pa[4][4];
#pragma unroll
        for (int j = 0; j < 4; j++) {
            const float e0 = __shfl_sync(0xffffffffu, p[j][0], psrc0);
            const float o0 = __shfl_sync(0xffffffffu, p[j][1], psrc0);
            const float e1 = __shfl_sync(0xffffffffu, p[j][2], psrc0);
            const float o1 = __shfl_sync(0xffffffffu, p[j][3], psrc0);
            const float e2 = __shfl_sync(0xffffffffu, p[j][0], psrc1);
            const float o2 = __shfl_sync(0xffffffffu, p[j][1], psrc1);
            const float e3 = __shfl_sync(0xffffffffu, p[j][2], psrc1);
            const float o3 = __shfl_sync(0xffffffffu, p[j][3], psrc1);
            pa[j][0] = __float_as_uint(podd ? o0 : e0);
            pa[j][1] = __float_as_uint(podd ? o1 : e1);
            pa[j][2] = __float_as_uint(podd ? o2 : e2);
            pa[j][3] = __float_as_uint(podd ? o3 : e3);
        }

        // O += P V   (kk-th k-slice of P is tile kk)
#pragma unroll
        for (int kk = 0; kk < 4; kk++) {
#pragma unroll
            for (int n = 0; n < 16; n++) {
                uint32_t bfr[2];
                bfr[0] = __float_as_uint(sV[(kk * 8 + gc) * VLD + n * 8 + gr]);
                bfr[1] = __float_as_uint(sV[(kk * 8 + gc + 4) * VLD + n * 8 + gr]);
                mma_tf32(o[n], pa[kk], bfr);
            }
        }
        __syncthreads();   // all warps done reading bufs[cur] before next iter overwrites
    }

    const float inv0 = 1.f / lst0;
    const float inv1 = 1.f / lst1;
#pragma unroll
    for (int n = 0; n < 16; n++) {
        const int col = h * HD + n * 8 + gc * 2;
        g_ctx[(size_t)irow0 * HIDDEN + col]           = cvt_tf32(o[n][0] * inv0);
        g_ctx[(size_t)irow0 * HIDDEN + col + 1]       = cvt_tf32(o[n][1] * inv0);
        g_ctx[(size_t)(irow0 + 8) * HIDDEN + col]     = cvt_tf32(o[n][2] * inv1);
        g_ctx[(size_t)(irow0 + 8) * HIDDEN + col + 1] = cvt_tf32(o[n][3] * inv1);
    }
}

// ---------------- launch ----------------
extern "C" void kernel_launch(void* const* d_in, const int* in_sizes, int n_in,
                              void* d_out, int out_size) {
    const float* hs = (const float*)d_in[0];
    const float* wq = (const float*)d_in[1];
    const float* wk = (const float*)d_in[2];
    const float* wv = (const float*)d_in[3];
    const float* wo = (const float*)d_in[4];
    float* out = (float*)d_out;

    cudaFuncSetAttribute(attn_kernel, cudaFuncAttributeMaxDynamicSharedMemorySize, ATTN_SMEM);

    prep_kernel<<<2048, 256>>>(hs, wq, wk, wv, wo);
    rope_table_kernel<<<SEQ, 64>>>();
    gemm_kernel<0><<<dim3(12, 32), 256>>>(nullptr);
    rope_kernel<<<(NH + NKV) * SEQ / 16, 256>>>();
    attn_kernel<<<512, 128, ATTN_SMEM>>>();
    gemm_kernel<1><<<dim3(8, 32), 256>>>(out);
}